// round 1
// baseline (speedup 1.0000x reference)
#include <cuda_runtime.h>
#include <cuda_bf16.h>
#include <math.h>

// Problem constants (registry-fixed shapes)
#define N_ROWS 8192
#define DIM    512
#define MARGIN 0.5f

// Scratch: normalized embeddings (fp32) + global accumulator
__device__ float  g_En[N_ROWS * DIM];
__device__ double g_sum;

// ---------------------------------------------------------------------------
// Kernel 0: zero the accumulator (must run every replay)
// ---------------------------------------------------------------------------
__global__ void zero_kernel() {
    g_sum = 0.0;
}

// ---------------------------------------------------------------------------
// Kernel 1: row-normalize embeddings. One block per row, 128 threads,
// one float4 per thread (DIM=512).
// ---------------------------------------------------------------------------
__global__ void normalize_kernel(const float* __restrict__ emb) {
    const int row = blockIdx.x;
    const int tid = threadIdx.x;
    const float4 v = reinterpret_cast<const float4*>(emb + (size_t)row * DIM)[tid];

    float ss = v.x * v.x + v.y * v.y + v.z * v.z + v.w * v.w;

    // warp reduce
    for (int off = 16; off > 0; off >>= 1)
        ss += __shfl_xor_sync(0xFFFFFFFF, ss, off);

    __shared__ float warp_sums[4];
    __shared__ float s_scale;
    const int lane = tid & 31;
    const int wid  = tid >> 5;
    if (lane == 0) warp_sums[wid] = ss;
    __syncthreads();
    if (tid == 0) {
        float tot = warp_sums[0] + warp_sums[1] + warp_sums[2] + warp_sums[3];
        float nrm = sqrtf(tot);
        s_scale = 1.0f / fmaxf(nrm, 1e-12f);
    }
    __syncthreads();
    const float sc = s_scale;

    float4 o;
    o.x = v.x * sc; o.y = v.y * sc; o.z = v.z * sc; o.w = v.w * sc;
    reinterpret_cast<float4*>(g_En + (size_t)row * DIM)[tid] = o;
}

// ---------------------------------------------------------------------------
// Kernel 2: symmetric tiled sim-GEMM fused with contrastive loss.
// 64x64 tile per block, 16x16 threads, 4x4 microtile per thread, BK=32.
// Only tiles with bj >= bi are computed; off-diagonal tiles weighted x2.
// ---------------------------------------------------------------------------
#define BK 32

__global__ __launch_bounds__(256) void loss_kernel(const int* __restrict__ labels) {
    const int bi = blockIdx.y;
    const int bj = blockIdx.x;
    if (bj < bi) return;

    const int rowBase = bi * 64;
    const int colBase = bj * 64;

    __shared__ float As[64][BK + 1];
    __shared__ float Bs[64][BK + 1];
    __shared__ int   s_rowLab[64];
    __shared__ int   s_colLab[64];

    const int tx  = threadIdx.x;   // 0..15
    const int ty  = threadIdx.y;   // 0..15
    const int tid = ty * 16 + tx;  // 0..255

    if (tid < 64)                 s_rowLab[tid]       = labels[rowBase + tid];
    else if (tid < 128)           s_colLab[tid - 64]  = labels[colBase + tid - 64];

    float acc[4][4];
#pragma unroll
    for (int i = 0; i < 4; i++)
#pragma unroll
        for (int j = 0; j < 4; j++) acc[i][j] = 0.0f;

    for (int k0 = 0; k0 < DIM; k0 += BK) {
        // Load 64xBK tiles of A and B (both from g_En). 512 float4 per tile,
        // 2 per thread.
#pragma unroll
        for (int p = 0; p < 2; p++) {
            const int e  = tid + p * 256;   // 0..511
            const int r  = e >> 3;          // row within tile
            const int c4 = (e & 7) << 2;    // col (multiple of 4)
            float4 va = *reinterpret_cast<const float4*>(
                g_En + (size_t)(rowBase + r) * DIM + k0 + c4);
            As[r][c4 + 0] = va.x; As[r][c4 + 1] = va.y;
            As[r][c4 + 2] = va.z; As[r][c4 + 3] = va.w;
            float4 vb = *reinterpret_cast<const float4*>(
                g_En + (size_t)(colBase + r) * DIM + k0 + c4);
            Bs[r][c4 + 0] = vb.x; Bs[r][c4 + 1] = vb.y;
            Bs[r][c4 + 2] = vb.z; Bs[r][c4 + 3] = vb.w;
        }
        __syncthreads();

#pragma unroll
        for (int kk = 0; kk < BK; kk++) {
            float a[4], b[4];
#pragma unroll
            for (int i = 0; i < 4; i++) a[i] = As[ty * 4 + i][kk];
#pragma unroll
            for (int j = 0; j < 4; j++) b[j] = Bs[tx * 4 + j][kk];
#pragma unroll
            for (int i = 0; i < 4; i++)
#pragma unroll
                for (int j = 0; j < 4; j++)
                    acc[i][j] = fmaf(a[i], b[j], acc[i][j]);
        }
        __syncthreads();
    }

    // Fused loss over the 4x4 microtile
    float local = 0.0f;
#pragma unroll
    for (int i = 0; i < 4; i++) {
        const int li = ty * 4 + i;
        const int gi = rowBase + li;
        const int la = s_rowLab[li];
#pragma unroll
        for (int j = 0; j < 4; j++) {
            const int lj = tx * 4 + j;
            const int gj = colBase + lj;
            if (gi == gj) continue;   // skip diagonal (self pairs)
            const float s = acc[i][j];
            float l;
            if (la == s_colLab[lj]) {
                const float d = 1.0f - s;
                l = d * d;
            } else {
                const float d = fmaxf(s - MARGIN, 0.0f);
                l = d * d;
            }
            local += l;
        }
    }
    if (bi != bj) local *= 2.0f;   // symmetric: (i,j) and (j,i)

    // Block reduction
    __shared__ float red[256];
    red[tid] = local;
    __syncthreads();
    for (int s = 128; s > 0; s >>= 1) {
        if (tid < s) red[tid] += red[tid + s];
        __syncthreads();
    }
    if (tid == 0) atomicAdd(&g_sum, (double)red[0]);
}

// ---------------------------------------------------------------------------
// Kernel 3: finalize — mean over N*(N-1) pairs.
// ---------------------------------------------------------------------------
__global__ void finalize_kernel(float* __restrict__ out) {
    const double num_pairs = (double)N_ROWS * (double)(N_ROWS - 1);
    out[0] = (float)(g_sum / num_pairs);
}

// ---------------------------------------------------------------------------
extern "C" void kernel_launch(void* const* d_in, const int* in_sizes, int n_in,
                              void* d_out, int out_size) {
    const float* embeddings = (const float*)d_in[0];
    const int*   labels     = (const int*)d_in[1];
    float*       out        = (float*)d_out;

    zero_kernel<<<1, 1>>>();
    normalize_kernel<<<N_ROWS, 128>>>(embeddings);

    dim3 grid(N_ROWS / 64, N_ROWS / 64);
    dim3 block(16, 16);
    loss_kernel<<<grid, block>>>(labels);

    finalize_kernel<<<1, 1>>>(out);
}

// round 3
// speedup vs baseline: 7.4395x; 7.4395x over previous
#include <cuda_runtime.h>
#include <cuda_bf16.h>
#include <math.h>
#include <cstdint>

#define N_ROWS 8192
#define DIM    512
#define MARGIN 0.5f

#define TILE   128
#define KC     64                      // K chunk (bf16 elems)
#define NCHUNK (DIM / KC)              // 8
#define NTILES (N_ROWS / TILE)         // 64
#define NBLOCKS (NTILES * (NTILES + 1) / 2)   // 2080

#define PITCH  (KC * 2 + 16)           // 144 B row pitch: bank-stride 4 -> ldmatrix conflict-free

// Scratch
__device__ __nv_bfloat16 g_Ebf[(size_t)N_ROWS * DIM];
__device__ double g_sum;

// ---------------------------------------------------------------------------
__device__ __forceinline__ uint32_t smem_u32(const void* p) {
    uint32_t a;
    asm("{ .reg .u64 t; cvta.to.shared.u64 t, %1; cvt.u32.u64 %0, t; }"
        : "=r"(a) : "l"(p));
    return a;
}

__device__ __forceinline__ void ldmx4(uint32_t* r, uint32_t addr) {
    asm volatile("ldmatrix.sync.aligned.m8n8.x4.shared.b16 {%0,%1,%2,%3}, [%4];"
                 : "=r"(r[0]), "=r"(r[1]), "=r"(r[2]), "=r"(r[3]) : "r"(addr));
}

__device__ __forceinline__ void mma16816(float* d, const uint32_t* a,
                                         uint32_t b0, uint32_t b1) {
    asm volatile(
        "mma.sync.aligned.m16n8k16.row.col.f32.bf16.bf16.f32 "
        "{%0,%1,%2,%3}, {%4,%5,%6,%7}, {%8,%9}, {%0,%1,%2,%3};"
        : "+f"(d[0]), "+f"(d[1]), "+f"(d[2]), "+f"(d[3])
        : "r"(a[0]), "r"(a[1]), "r"(a[2]), "r"(a[3]), "r"(b0), "r"(b1));
}

// ---------------------------------------------------------------------------
__global__ void zero_kernel() { g_sum = 0.0; }

// ---------------------------------------------------------------------------
// Kernel 1: normalize + convert to bf16
// ---------------------------------------------------------------------------
__global__ void normalize_kernel(const float* __restrict__ emb) {
    const int row = blockIdx.x;
    const int tid = threadIdx.x;   // 128 threads, 4 floats each
    const float4 v = reinterpret_cast<const float4*>(emb + (size_t)row * DIM)[tid];

    float ss = v.x*v.x + v.y*v.y + v.z*v.z + v.w*v.w;
    for (int off = 16; off > 0; off >>= 1)
        ss += __shfl_xor_sync(0xFFFFFFFF, ss, off);

    __shared__ float warp_sums[4];
    __shared__ float s_scale;
    if ((tid & 31) == 0) warp_sums[tid >> 5] = ss;
    __syncthreads();
    if (tid == 0) {
        float tot = warp_sums[0] + warp_sums[1] + warp_sums[2] + warp_sums[3];
        s_scale = 1.0f / fmaxf(sqrtf(tot), 1e-12f);
    }
    __syncthreads();
    const float sc = s_scale;

    __nv_bfloat162 p0 = __floats2bfloat162_rn(v.x * sc, v.y * sc);
    __nv_bfloat162 p1 = __floats2bfloat162_rn(v.z * sc, v.w * sc);
    uint2 o;
    o.x = *reinterpret_cast<uint32_t*>(&p0);
    o.y = *reinterpret_cast<uint32_t*>(&p1);
    reinterpret_cast<uint2*>(g_Ebf + (size_t)row * DIM)[tid] = o;
}

// ---------------------------------------------------------------------------
// Kernel 2: mma.sync bf16 sim-GEMM over upper triangle, fused loss.
// 256 threads = 8 warps in 2x4: warp computes 64x32 via 4x4 HMMA.16816 grid.
// ---------------------------------------------------------------------------
#define SM_RLAB 0
#define SM_CLAB 512
#define SM_RED  1024
#define SM_A    1088
#define SM_B    (SM_A + TILE * PITCH)          // 1088 + 18432
#define SM_TOT  (SM_B + TILE * PITCH)          // ~37.9 KB

__global__ __launch_bounds__(256, 2) void loss_kernel(const int* __restrict__ labels) {
    extern __shared__ char smem[];
    const uint32_t sbase = smem_u32(smem);
    const int tid  = threadIdx.x;
    const int wid  = tid >> 5;
    const int lane = tid & 31;
    const int wr   = wid >> 2;    // 0..1 warp row
    const int wc   = wid & 3;     // 0..3 warp col

    // Triangular decode blockIdx.x -> (bi, bj), bj >= bi
    int idx = blockIdx.x;
    int bi = (int)((2.0f * NTILES + 1.0f
                    - sqrtf((2.0f*NTILES+1.0f)*(2.0f*NTILES+1.0f) - 8.0f*idx)) * 0.5f);
    while (bi > 0 && bi * NTILES - (bi * (bi - 1)) / 2 > idx) bi--;
    while ((bi + 1) * NTILES - ((bi + 1) * bi) / 2 <= idx) bi++;
    const int bj = bi + (idx - (bi * NTILES - (bi * (bi - 1)) / 2));

    const int rowBase = bi * TILE;
    const int colBase = bj * TILE;

    int* sRlab = reinterpret_cast<int*>(smem + SM_RLAB);
    int* sClab = reinterpret_cast<int*>(smem + SM_CLAB);
    if (tid < 128)       sRlab[tid]        = labels[rowBase + tid];
    else                 sClab[tid - 128]  = labels[colBase + (tid - 128)];

    // Per-lane ldmatrix base addresses (row part fixed, k offset varies)
    // A: rows wr*64 + mi*16 + (lane&15), col-half +16B if lane>=16
    const int lrow = lane & 15;
    const uint32_t khalf = (lane & 16) ? 16u : 0u;
    const uint32_t aAddr = sbase + SM_A + (uint32_t)(wr * 64 + lrow) * PITCH + khalf;
    const uint32_t bAddr = sbase + SM_B + (uint32_t)(wc * 32 + lrow) * PITCH + khalf;

    float acc[4][4][4];
#pragma unroll
    for (int i = 0; i < 4; i++)
#pragma unroll
        for (int j = 0; j < 4; j++)
#pragma unroll
            for (int q = 0; q < 4; q++) acc[i][j][q] = 0.0f;

    for (int c = 0; c < NCHUNK; c++) {
        // gmem -> smem: 2 tiles x 128 rows x 8 uint4 = 2048 uint4, 8/thread
#pragma unroll
        for (int p = 0; p < 8; p++) {
            const int e   = tid + p * 256;      // 0..2047
            const int isB = e >> 10;
            const int w   = e & 1023;
            const int r   = w >> 3;             // 0..127
            const int g   = w & 7;              // 16B group
            const int gro = (isB ? colBase : rowBase) + r;
            const uint4 v = *reinterpret_cast<const uint4*>(
                g_Ebf + (size_t)gro * DIM + c * KC + g * 8);
            *reinterpret_cast<uint4*>(smem + (isB ? SM_B : SM_A) + r * PITCH + g * 16) = v;
        }
        __syncthreads();

#pragma unroll
        for (int ks = 0; ks < KC / 16; ks++) {
            const uint32_t ko = ks * 32;  // bytes
            uint32_t a[4][4];
#pragma unroll
            for (int mi = 0; mi < 4; mi++)
                ldmx4(a[mi], aAddr + (uint32_t)(mi * 16) * PITCH + ko);
            uint32_t b[2][4];
#pragma unroll
            for (int nb = 0; nb < 2; nb++)
                ldmx4(b[nb], bAddr + (uint32_t)(nb * 16) * PITCH + ko);
#pragma unroll
            for (int mi = 0; mi < 4; mi++) {
#pragma unroll
                for (int ni = 0; ni < 4; ni++) {
                    const uint32_t b0 = b[ni >> 1][ni & 1];
                    const uint32_t b1 = b[ni >> 1][2 + (ni & 1)];
                    mma16816(acc[mi][ni], a[mi], b0, b1);
                }
            }
        }
        __syncthreads();
    }

    // ---- fused loss epilogue on register fragments ----
    float local = 0.0f;
#pragma unroll
    for (int mi = 0; mi < 4; mi++) {
        const int r0 = wr * 64 + mi * 16 + (lane >> 2);
#pragma unroll
        for (int ni = 0; ni < 4; ni++) {
            const int c0 = wc * 32 + ni * 8 + ((lane & 3) << 1);
#pragma unroll
            for (int h = 0; h < 2; h++) {
                const int ri = r0 + h * 8;
                const int gi = rowBase + ri;
                const int la = sRlab[ri];
#pragma unroll
                for (int q = 0; q < 2; q++) {
                    const int cj = c0 + q;
                    const int gj = colBase + cj;
                    if (gi == gj) continue;
                    const float s = acc[mi][ni][h * 2 + q];
                    float dd;
                    if (la == sClab[cj]) dd = 1.0f - s;
                    else                 dd = fmaxf(s - MARGIN, 0.0f);
                    local += dd * dd;
                }
            }
        }
    }
    if (bi != bj) local *= 2.0f;   // symmetric tile counted twice

    // reduce: warp -> block -> global
    for (int off = 16; off > 0; off >>= 1)
        local += __shfl_xor_sync(0xFFFFFFFF, local, off);
    float* sRed = reinterpret_cast<float*>(smem + SM_RED);
    if (lane == 0) sRed[wid] = local;
    __syncthreads();
    if (tid == 0) {
        float t = 0.0f;
#pragma unroll
        for (int w = 0; w < 8; w++) t += sRed[w];
        atomicAdd(&g_sum, (double)t);
    }
}

// ---------------------------------------------------------------------------
__global__ void finalize_kernel(float* __restrict__ out) {
    const double num_pairs = (double)N_ROWS * (double)(N_ROWS - 1);
    out[0] = (float)(g_sum / num_pairs);
}

// ---------------------------------------------------------------------------
extern "C" void kernel_launch(void* const* d_in, const int* in_sizes, int n_in,
                              void* d_out, int out_size) {
    const float* embeddings = (const float*)d_in[0];
    const int*   labels     = (const int*)d_in[1];
    float*       out        = (float*)d_out;

    zero_kernel<<<1, 1>>>();
    normalize_kernel<<<N_ROWS, 128>>>(embeddings);
    loss_kernel<<<NBLOCKS, 256, SM_TOT>>>(labels);
    finalize_kernel<<<1, 1>>>(out);
}

// round 5
// speedup vs baseline: 7.4545x; 1.0020x over previous
#include <cuda_runtime.h>
#include <cuda_bf16.h>
#include <math.h>
#include <cstdint>

#define N_ROWS 8192
#define DIM    512
#define MARGIN 0.5f

#define TILE   128
#define KC     64                      // K chunk (bf16 elems)
#define NCHUNK (DIM / KC)              // 8
#define NTILES (N_ROWS / TILE)         // 64
#define NBLOCKS (NTILES * (NTILES + 1) / 2)   // 2080

#define PITCH  (KC * 2 + 16)           // 144 B row pitch: bank-stride 4 -> ldmatrix conflict-free

// Scratch
__device__ __nv_bfloat16 g_Ebf[(size_t)N_ROWS * DIM];
__device__ double g_sum;

// ---------------------------------------------------------------------------
__device__ __forceinline__ uint32_t smem_u32(const void* p) {
    uint32_t a;
    asm("{ .reg .u64 t; cvta.to.shared.u64 t, %1; cvt.u32.u64 %0, t; }"
        : "=r"(a) : "l"(p));
    return a;
}

__device__ __forceinline__ void ldmx4(uint32_t* r, uint32_t addr) {
    asm volatile("ldmatrix.sync.aligned.m8n8.x4.shared.b16 {%0,%1,%2,%3}, [%4];"
                 : "=r"(r[0]), "=r"(r[1]), "=r"(r[2]), "=r"(r[3]) : "r"(addr));
}

__device__ __forceinline__ void mma16816(float* d, const uint32_t* a,
                                         uint32_t b0, uint32_t b1) {
    asm volatile(
        "mma.sync.aligned.m16n8k16.row.col.f32.bf16.bf16.f32 "
        "{%0,%1,%2,%3}, {%4,%5,%6,%7}, {%8,%9}, {%0,%1,%2,%3};"
        : "+f"(d[0]), "+f"(d[1]), "+f"(d[2]), "+f"(d[3])
        : "r"(a[0]), "r"(a[1]), "r"(a[2]), "r"(a[3]), "r"(b0), "r"(b1));
}

// ---------------------------------------------------------------------------
__global__ void zero_kernel() { g_sum = 0.0; }

// ---------------------------------------------------------------------------
// Kernel 1: normalize + convert to bf16
// ---------------------------------------------------------------------------
__global__ void normalize_kernel(const float* __restrict__ emb) {
    const int row = blockIdx.x;
    const int tid = threadIdx.x;   // 128 threads, 4 floats each
    const float4 v = reinterpret_cast<const float4*>(emb + (size_t)row * DIM)[tid];

    float ss = v.x*v.x + v.y*v.y + v.z*v.z + v.w*v.w;
    for (int off = 16; off > 0; off >>= 1)
        ss += __shfl_xor_sync(0xFFFFFFFF, ss, off);

    __shared__ float warp_sums[4];
    __shared__ float s_scale;
    if ((tid & 31) == 0) warp_sums[tid >> 5] = ss;
    __syncthreads();
    if (tid == 0) {
        float tot = warp_sums[0] + warp_sums[1] + warp_sums[2] + warp_sums[3];
        s_scale = 1.0f / fmaxf(sqrtf(tot), 1e-12f);
    }
    __syncthreads();
    const float sc = s_scale;

    __nv_bfloat162 p0 = __floats2bfloat162_rn(v.x * sc, v.y * sc);
    __nv_bfloat162 p1 = __floats2bfloat162_rn(v.z * sc, v.w * sc);
    uint2 o;
    o.x = *reinterpret_cast<uint32_t*>(&p0);
    o.y = *reinterpret_cast<uint32_t*>(&p1);
    reinterpret_cast<uint2*>(g_Ebf + (size_t)row * DIM)[tid] = o;
}

// ---------------------------------------------------------------------------
// Kernel 2: mma.sync bf16 sim-GEMM over upper triangle, fused loss.
// 256 threads = 8 warps in 2x4: warp computes 64x32 via 4x4 HMMA.16816 grid.
// ---------------------------------------------------------------------------
#define SM_RLAB 0
#define SM_CLAB 512
#define SM_RED  1024
#define SM_A    1088
#define SM_B    (SM_A + TILE * PITCH)          // 1088 + 18432
#define SM_TOT  (SM_B + TILE * PITCH)          // ~37.9 KB

__global__ __launch_bounds__(256, 2) void loss_kernel(const int* __restrict__ labels) {
    extern __shared__ char smem[];
    const uint32_t sbase = smem_u32(smem);
    const int tid  = threadIdx.x;
    const int wid  = tid >> 5;
    const int lane = tid & 31;
    const int wr   = wid >> 2;    // 0..1 warp row
    const int wc   = wid & 3;     // 0..3 warp col

    // Triangular decode blockIdx.x -> (bi, bj), bj >= bi
    int idx = blockIdx.x;
    int bi = (int)((2.0f * NTILES + 1.0f
                    - sqrtf((2.0f*NTILES+1.0f)*(2.0f*NTILES+1.0f) - 8.0f*idx)) * 0.5f);
    while (bi > 0 && bi * NTILES - (bi * (bi - 1)) / 2 > idx) bi--;
    while ((bi + 1) * NTILES - ((bi + 1) * bi) / 2 <= idx) bi++;
    const int bj = bi + (idx - (bi * NTILES - (bi * (bi - 1)) / 2));

    const int rowBase = bi * TILE;
    const int colBase = bj * TILE;

    int* sRlab = reinterpret_cast<int*>(smem + SM_RLAB);
    int* sClab = reinterpret_cast<int*>(smem + SM_CLAB);
    if (tid < 128)       sRlab[tid]        = labels[rowBase + tid];
    else                 sClab[tid - 128]  = labels[colBase + (tid - 128)];

    // Per-lane ldmatrix base addresses (row part fixed, k offset varies)
    // A: rows wr*64 + mi*16 + (lane&15), col-half +16B if lane>=16
    const int lrow = lane & 15;
    const uint32_t khalf = (lane & 16) ? 16u : 0u;
    const uint32_t aAddr = sbase + SM_A + (uint32_t)(wr * 64 + lrow) * PITCH + khalf;
    const uint32_t bAddr = sbase + SM_B + (uint32_t)(wc * 32 + lrow) * PITCH + khalf;

    float acc[4][4][4];
#pragma unroll
    for (int i = 0; i < 4; i++)
#pragma unroll
        for (int j = 0; j < 4; j++)
#pragma unroll
            for (int q = 0; q < 4; q++) acc[i][j][q] = 0.0f;

    for (int c = 0; c < NCHUNK; c++) {
        // gmem -> smem: 2 tiles x 128 rows x 8 uint4 = 2048 uint4, 8/thread
#pragma unroll
        for (int p = 0; p < 8; p++) {
            const int e   = tid + p * 256;      // 0..2047
            const int isB = e >> 10;
            const int w   = e & 1023;
            const int r   = w >> 3;             // 0..127
            const int g   = w & 7;              // 16B group
            const int gro = (isB ? colBase : rowBase) + r;
            const uint4 v = *reinterpret_cast<const uint4*>(
                g_Ebf + (size_t)gro * DIM + c * KC + g * 8);
            *reinterpret_cast<uint4*>(smem + (isB ? SM_B : SM_A) + r * PITCH + g * 16) = v;
        }
        __syncthreads();

#pragma unroll
        for (int ks = 0; ks < KC / 16; ks++) {
            const uint32_t ko = ks * 32;  // bytes
            uint32_t a[4][4];
#pragma unroll
            for (int mi = 0; mi < 4; mi++)
                ldmx4(a[mi], aAddr + (uint32_t)(mi * 16) * PITCH + ko);
            uint32_t b[2][4];
#pragma unroll
            for (int nb = 0; nb < 2; nb++)
                ldmx4(b[nb], bAddr + (uint32_t)(nb * 16) * PITCH + ko);
#pragma unroll
            for (int mi = 0; mi < 4; mi++) {
#pragma unroll
                for (int ni = 0; ni < 4; ni++) {
                    const uint32_t b0 = b[ni >> 1][ni & 1];
                    const uint32_t b1 = b[ni >> 1][2 + (ni & 1)];
                    mma16816(acc[mi][ni], a[mi], b0, b1);
                }
            }
        }
        __syncthreads();
    }

    // ---- fused loss epilogue on register fragments ----
    float local = 0.0f;
#pragma unroll
    for (int mi = 0; mi < 4; mi++) {
        const int r0 = wr * 64 + mi * 16 + (lane >> 2);
#pragma unroll
        for (int ni = 0; ni < 4; ni++) {
            const int c0 = wc * 32 + ni * 8 + ((lane & 3) << 1);
#pragma unroll
            for (int h = 0; h < 2; h++) {
                const int ri = r0 + h * 8;
                const int gi = rowBase + ri;
                const int la = sRlab[ri];
#pragma unroll
                for (int q = 0; q < 2; q++) {
                    const int cj = c0 + q;
                    const int gj = colBase + cj;
                    if (gi == gj) continue;
                    const float s = acc[mi][ni][h * 2 + q];
                    float dd;
                    if (la == sClab[cj]) dd = 1.0f - s;
                    else                 dd = fmaxf(s - MARGIN, 0.0f);
                    local += dd * dd;
                }
            }
        }
    }
    if (bi != bj) local *= 2.0f;   // symmetric tile counted twice

    // reduce: warp -> block -> global
    for (int off = 16; off > 0; off >>= 1)
        local += __shfl_xor_sync(0xFFFFFFFF, local, off);
    float* sRed = reinterpret_cast<float*>(smem + SM_RED);
    if (lane == 0) sRed[wid] = local;
    __syncthreads();
    if (tid == 0) {
        float t = 0.0f;
#pragma unroll
        for (int w = 0; w < 8; w++) t += sRed[w];
        atomicAdd(&g_sum, (double)t);
    }
}

// ---------------------------------------------------------------------------
__global__ void finalize_kernel(float* __restrict__ out) {
    const double num_pairs = (double)N_ROWS * (double)(N_ROWS - 1);
    out[0] = (float)(g_sum / num_pairs);
}

// ---------------------------------------------------------------------------
extern "C" void kernel_launch(void* const* d_in, const int* in_sizes, int n_in,
                              void* d_out, int out_size) {
    const float* embeddings = (const float*)d_in[0];
    const int*   labels     = (const int*)d_in[1];
    float*       out        = (float*)d_out;

    zero_kernel<<<1, 1>>>();
    normalize_kernel<<<N_ROWS, 128>>>(embeddings);
    loss_kernel<<<NBLOCKS, 256, SM_TOT>>>(labels);
    finalize_kernel<<<1, 1>>>(out);
}

// round 6
// speedup vs baseline: 7.5456x; 1.0122x over previous
#include <cuda_runtime.h>
#include <cuda_bf16.h>
#include <math.h>
#include <cstdint>

#define N_ROWS 8192
#define DIM    512
#define MARGIN 0.5f

#define TILE   128
#define KC     64                      // K chunk (bf16 elems)
#define NCHUNK (DIM / KC)              // 8
#define NTILES (N_ROWS / TILE)         // 64
#define NBLOCKS (NTILES * (NTILES + 1) / 2)   // 2080

#define PITCH  (KC * 2 + 16)           // 144 B row pitch (16B-aligned, ldmatrix conflict-free)

// Scratch
__device__ __nv_bfloat16 g_Ebf[(size_t)N_ROWS * DIM];
__device__ double g_sum;

// ---------------------------------------------------------------------------
__device__ __forceinline__ uint32_t smem_u32(const void* p) {
    uint32_t a;
    asm("{ .reg .u64 t; cvta.to.shared.u64 t, %1; cvt.u32.u64 %0, t; }"
        : "=r"(a) : "l"(p));
    return a;
}

__device__ __forceinline__ void ldmx4(uint32_t* r, uint32_t addr) {
    asm volatile("ldmatrix.sync.aligned.m8n8.x4.shared.b16 {%0,%1,%2,%3}, [%4];"
                 : "=r"(r[0]), "=r"(r[1]), "=r"(r[2]), "=r"(r[3]) : "r"(addr));
}

__device__ __forceinline__ void mma16816(float* d, const uint32_t* a,
                                         uint32_t b0, uint32_t b1) {
    asm volatile(
        "mma.sync.aligned.m16n8k16.row.col.f32.bf16.bf16.f32 "
        "{%0,%1,%2,%3}, {%4,%5,%6,%7}, {%8,%9}, {%0,%1,%2,%3};"
        : "+f"(d[0]), "+f"(d[1]), "+f"(d[2]), "+f"(d[3])
        : "r"(a[0]), "r"(a[1]), "r"(a[2]), "r"(a[3]), "r"(b0), "r"(b1));
}

__device__ __forceinline__ void cp_async16(uint32_t smem_dst, const void* gmem_src) {
    asm volatile("cp.async.cg.shared.global [%0], [%1], 16;"
                 :: "r"(smem_dst), "l"(gmem_src) : "memory");
}
__device__ __forceinline__ void cp_commit() {
    asm volatile("cp.async.commit_group;" ::: "memory");
}
template <int N>
__device__ __forceinline__ void cp_wait() {
    asm volatile("cp.async.wait_group %0;" :: "n"(N) : "memory");
}

// ---------------------------------------------------------------------------
// Kernel 1: normalize + convert to bf16 (+ zero the accumulator from block 0)
// ---------------------------------------------------------------------------
__global__ void normalize_kernel(const float* __restrict__ emb) {
    const int row = blockIdx.x;
    const int tid = threadIdx.x;   // 128 threads, 4 floats each
    if (row == 0 && tid == 0) g_sum = 0.0;   // ordered before loss_kernel (stream serializes)

    const float4 v = reinterpret_cast<const float4*>(emb + (size_t)row * DIM)[tid];

    float ss = v.x*v.x + v.y*v.y + v.z*v.z + v.w*v.w;
    for (int off = 16; off > 0; off >>= 1)
        ss += __shfl_xor_sync(0xFFFFFFFF, ss, off);

    __shared__ float warp_sums[4];
    __shared__ float s_scale;
    if ((tid & 31) == 0) warp_sums[tid >> 5] = ss;
    __syncthreads();
    if (tid == 0) {
        float tot = warp_sums[0] + warp_sums[1] + warp_sums[2] + warp_sums[3];
        s_scale = 1.0f / fmaxf(sqrtf(tot), 1e-12f);
    }
    __syncthreads();
    const float sc = s_scale;

    __nv_bfloat162 p0 = __floats2bfloat162_rn(v.x * sc, v.y * sc);
    __nv_bfloat162 p1 = __floats2bfloat162_rn(v.z * sc, v.w * sc);
    uint2 o;
    o.x = *reinterpret_cast<uint32_t*>(&p0);
    o.y = *reinterpret_cast<uint32_t*>(&p1);
    reinterpret_cast<uint2*>(g_Ebf + (size_t)row * DIM)[tid] = o;
}

// ---------------------------------------------------------------------------
// Kernel 2: mma.sync bf16 sim-GEMM over upper triangle, fused loss.
// cp.async double-buffered K pipeline. 8 warps (2x4), warp tile 64x32.
// ---------------------------------------------------------------------------
#define SM_RLAB 0
#define SM_CLAB 512
#define SM_RED  1024
#define SM_BUF  1088
#define BUFSZ   (2 * TILE * PITCH)     // A+B per stage: 36864 B
#define SM_TOT  (SM_BUF + 2 * BUFSZ)   // 74816 B

__global__ __launch_bounds__(256, 2) void loss_kernel(const int* __restrict__ labels) {
    extern __shared__ char smem[];
    const uint32_t sbase = smem_u32(smem);
    const int tid  = threadIdx.x;
    const int wid  = tid >> 5;
    const int lane = tid & 31;
    const int wr   = wid >> 2;    // 0..1 warp row
    const int wc   = wid & 3;     // 0..3 warp col

    // Triangular decode blockIdx.x -> (bi, bj), bj >= bi
    int idx = blockIdx.x;
    int bi = (int)((2.0f * NTILES + 1.0f
                    - sqrtf((2.0f*NTILES+1.0f)*(2.0f*NTILES+1.0f) - 8.0f*idx)) * 0.5f);
    while (bi > 0 && bi * NTILES - (bi * (bi - 1)) / 2 > idx) bi--;
    while ((bi + 1) * NTILES - ((bi + 1) * bi) / 2 <= idx) bi++;
    const int bj = bi + (idx - (bi * NTILES - (bi * (bi - 1)) / 2));

    const int rowBase = bi * TILE;
    const int colBase = bj * TILE;

    int* sRlab = reinterpret_cast<int*>(smem + SM_RLAB);
    int* sClab = reinterpret_cast<int*>(smem + SM_CLAB);
    if (tid < 128)       sRlab[tid]        = labels[rowBase + tid];
    else                 sClab[tid - 128]  = labels[colBase + (tid - 128)];

    // Per-thread cp.async source/dst mapping: 8 x 16B per thread per chunk.
    // e = tid + p*256 in [0,2048): isB = e>>10, r = (e&1023)>>3, g = e&7.
    // Precompute row/group decompositions.
    int cp_row[8]; int cp_isB[8]; int cp_g[8];
#pragma unroll
    for (int p = 0; p < 8; p++) {
        const int e = tid + p * 256;
        cp_isB[p] = e >> 10;
        cp_row[p] = (e & 1023) >> 3;
        cp_g[p]   = e & 7;
    }

    // ldmatrix per-lane bases (relative to buffer start)
    const int lrow = lane & 15;
    const uint32_t khalf = (lane & 16) ? 16u : 0u;
    const uint32_t aRel = (uint32_t)(wr * 64 + lrow) * PITCH + khalf;
    const uint32_t bRel = (uint32_t)(TILE * PITCH) + (uint32_t)(wc * 32 + lrow) * PITCH + khalf;

    float acc[4][4][4];
#pragma unroll
    for (int i = 0; i < 4; i++)
#pragma unroll
        for (int j = 0; j < 4; j++)
#pragma unroll
            for (int q = 0; q < 4; q++) acc[i][j][q] = 0.0f;

    // ---- prefetch chunk 0 into buffer 0 ----
#pragma unroll
    for (int p = 0; p < 8; p++) {
        const int gro = (cp_isB[p] ? colBase : rowBase) + cp_row[p];
        const uint32_t dst = sbase + SM_BUF
            + (uint32_t)(cp_isB[p] * (TILE * PITCH) + cp_row[p] * PITCH + cp_g[p] * 16);
        cp_async16(dst, g_Ebf + (size_t)gro * DIM + cp_g[p] * 8);
    }
    cp_commit();

#pragma unroll 1
    for (int c = 0; c < NCHUNK; c++) {
        const uint32_t curBuf = sbase + SM_BUF + (uint32_t)((c & 1) * BUFSZ);

        if (c + 1 < NCHUNK) {
            const uint32_t nxtBuf = sbase + SM_BUF + (uint32_t)(((c + 1) & 1) * BUFSZ);
            const int koff = (c + 1) * KC;
#pragma unroll
            for (int p = 0; p < 8; p++) {
                const int gro = (cp_isB[p] ? colBase : rowBase) + cp_row[p];
                const uint32_t dst = nxtBuf
                    + (uint32_t)(cp_isB[p] * (TILE * PITCH) + cp_row[p] * PITCH + cp_g[p] * 16);
                cp_async16(dst, g_Ebf + (size_t)gro * DIM + koff + cp_g[p] * 8);
            }
            cp_commit();
            cp_wait<1>();   // current chunk's group complete
        } else {
            cp_wait<0>();
        }
        __syncthreads();

        const uint32_t aAddr = curBuf + aRel;
        const uint32_t bAddr = curBuf + bRel;
#pragma unroll
        for (int ks = 0; ks < KC / 16; ks++) {
            const uint32_t ko = ks * 32;  // bytes
            uint32_t a[4][4];
#pragma unroll
            for (int mi = 0; mi < 4; mi++)
                ldmx4(a[mi], aAddr + (uint32_t)(mi * 16) * PITCH + ko);
            uint32_t b[2][4];
#pragma unroll
            for (int nb = 0; nb < 2; nb++)
                ldmx4(b[nb], bAddr + (uint32_t)(nb * 16) * PITCH + ko);
#pragma unroll
            for (int mi = 0; mi < 4; mi++) {
#pragma unroll
                for (int ni = 0; ni < 4; ni++) {
                    const uint32_t b0 = b[ni >> 1][ni & 1];
                    const uint32_t b1 = b[ni >> 1][2 + (ni & 1)];
                    mma16816(acc[mi][ni], a[mi], b0, b1);
                }
            }
        }
        __syncthreads();   // all warps done with curBuf before it is refilled
    }

    // ---- fused loss epilogue on register fragments ----
    float local = 0.0f;
#pragma unroll
    for (int mi = 0; mi < 4; mi++) {
        const int r0 = wr * 64 + mi * 16 + (lane >> 2);
#pragma unroll
        for (int ni = 0; ni < 4; ni++) {
            const int c0 = wc * 32 + ni * 8 + ((lane & 3) << 1);
#pragma unroll
            for (int h = 0; h < 2; h++) {
                const int ri = r0 + h * 8;
                const int gi = rowBase + ri;
                const int la = sRlab[ri];
#pragma unroll
                for (int q = 0; q < 2; q++) {
                    const int cj = c0 + q;
                    const int gj = colBase + cj;
                    if (gi == gj) continue;
                    const float s = acc[mi][ni][h * 2 + q];
                    float dd;
                    if (la == sClab[cj]) dd = 1.0f - s;
                    else                 dd = fmaxf(s - MARGIN, 0.0f);
                    local += dd * dd;
                }
            }
        }
    }
    if (bi != bj) local *= 2.0f;   // symmetric tile counted twice

    // reduce: warp -> block -> global
    for (int off = 16; off > 0; off >>= 1)
        local += __shfl_xor_sync(0xFFFFFFFF, local, off);
    float* sRed = reinterpret_cast<float*>(smem + SM_RED);
    if (lane == 0) sRed[wid] = local;
    __syncthreads();
    if (tid == 0) {
        float t = 0.0f;
#pragma unroll
        for (int w = 0; w < 8; w++) t += sRed[w];
        atomicAdd(&g_sum, (double)t);
    }
}

// ---------------------------------------------------------------------------
__global__ void finalize_kernel(float* __restrict__ out) {
    const double num_pairs = (double)N_ROWS * (double)(N_ROWS - 1);
    out[0] = (float)(g_sum / num_pairs);
}

// ---------------------------------------------------------------------------
extern "C" void kernel_launch(void* const* d_in, const int* in_sizes, int n_in,
                              void* d_out, int out_size) {
    const float* embeddings = (const float*)d_in[0];
    const int*   labels     = (const int*)d_in[1];
    float*       out        = (float*)d_out;

    static bool attr_set = false;
    if (!attr_set) {
        cudaFuncSetAttribute(loss_kernel,
                             cudaFuncAttributeMaxDynamicSharedMemorySize, SM_TOT);
        attr_set = true;
    }

    normalize_kernel<<<N_ROWS, 128>>>(embeddings);
    loss_kernel<<<NBLOCKS, 256, SM_TOT>>>(labels);
    finalize_kernel<<<1, 1>>>(out);
}